// round 4
// baseline (speedup 1.0000x reference)
#include <cuda_runtime.h>
#include <cstdint>
#include <math.h>

#define NS   400000
#define NTHR 256
#define NB1  1563               // ceil(NS/256) blocks for k1
#define NB3  1563               // blocks for k3
#define NQ   41                 // 1 (loss1) + 4*10 GMM stats

// ---------------- device scratch (no allocations allowed) ----------------
__device__ float g_scratch[NB1 * 48];   // per-block stat partials
__device__ float g_z[3 * NS];           // z components, SoA
__device__ float g_params[48];          // per-k params + loss partial
__device__ float g_esum[NB3];           // per-block energy partials
__device__ int   g_cnt1 = 0;            // last-block tickets (self-resetting)
__device__ int   g_cnt3 = 0;

typedef unsigned long long ull;

// ---------------- helpers ----------------
__device__ __forceinline__ ull pk2(float a, float b) {
    ull r; asm("mov.b64 %0, {%1, %2};" : "=l"(r) : "f"(a), "f"(b)); return r;
}
__device__ __forceinline__ void upk(ull v, float& a, float& b) {
    asm("mov.b64 {%0, %1}, %2;" : "=f"(a), "=f"(b) : "l"(v));
}
__device__ __forceinline__ void ffma2(ull& d, ull a, ull b) {
    asm("fma.rn.f32x2 %0, %1, %2, %0;" : "+l"(d) : "l"(a), "l"(b));
}
__device__ __forceinline__ float tanh_fast(float x) {
    float e = __expf(2.0f * x);
    return 1.0f - __fdividef(2.0f, e + 1.0f);
}
__device__ __forceinline__ float warp_sum(float v) {
#pragma unroll
    for (int o = 16; o > 0; o >>= 1) v += __shfl_down_sync(0xffffffffu, v, o);
    return v;
}
__device__ __forceinline__ double warp_dsum(double v) {
#pragma unroll
    for (int o = 16; o > 0; o >>= 1) v += __shfl_down_sync(0xffffffffu, v, o);
    return v;
}

// ---------------- K1: fused forward + stats + (last block) GMM params ----------------
__global__ __launch_bounds__(NTHR) void k1(
    const float* __restrict__ x1,
    const float* __restrict__ ew1, const float* __restrict__ eb1,
    const float* __restrict__ ew2, const float* __restrict__ eb2,
    const float* __restrict__ ew3, const float* __restrict__ eb3,
    const float* __restrict__ dw1, const float* __restrict__ db1,
    const float* __restrict__ dw2, const float* __restrict__ db2,
    const float* __restrict__ dw3, const float* __restrict__ db3,
    const float* __restrict__ tw1, const float* __restrict__ tb1,
    const float* __restrict__ tw2, const float* __restrict__ tb2)
{
    __shared__ __align__(16) float sWc[4096];      // [128][32]: [enc_w1 | dec_w3^T]
    __shared__ float sX[NTHR * 17];                // staged x tile, stride 17 (conflict-free)
    __shared__ __align__(16) float sM[256];        // dec_w3 @ dec_w3^T
    __shared__ __align__(16) float sB3[128];
    __shared__ float sV[16];
    __shared__ float sEB1[16], sEW2[128], sEB2[8], sEW3[8];
    __shared__ float sDW1[8], sDB1[8], sDW2[128], sDB2[16];
    __shared__ float sTW1[24], sTB1[8], sTW2[32], sTB2[4];
    __shared__ float sEB3, sBB;
    __shared__ float sWred[NQ][8];
    __shared__ double sTot[NQ];
    __shared__ double sL3[4];
    __shared__ int sIsLast;

    const int tid = threadIdx.x;
    const int lane = tid & 31, wid = tid >> 5;

    // ---- load weights (fused layout built on the fly) ----
    for (int idx = tid; idx < 4096; idx += NTHR) {
        int i = idx >> 5, c = idx & 31;
        sWc[idx] = (c < 16) ? ew1[i * 16 + c] : dw3[(c - 16) * 128 + i];
    }
    if (tid < 128) { sB3[tid] = db3[tid]; sEW2[tid] = ew2[tid]; sDW2[tid] = dw2[tid]; }
    if (tid < 16)  { sEB1[tid] = eb1[tid]; sDB2[tid] = db2[tid]; }
    if (tid < 8)   { sEB2[tid] = eb2[tid]; sEW3[tid] = ew3[tid];
                     sDW1[tid] = dw1[tid]; sDB1[tid] = db1[tid]; sTB1[tid] = tb1[tid]; }
    if (tid < 24)  sTW1[tid] = tw1[tid];
    if (tid < 32)  sTW2[tid] = tw2[tid];
    if (tid < 4)   sTB2[tid] = tb2[tid];
    if (tid == 0)  sEB3 = eb3[0];
    __syncthreads();

    // ---- per-block decoder-algebra constants (cheap: ~128 FMA/thread, from smem) ----
    {
        int j = tid >> 4, l = tid & 15;
        float s = 0.0f;
#pragma unroll 8
        for (int i = 0; i < 128; i++)
            s += sWc[i * 32 + 16 + j] * sWc[i * 32 + 16 + l];
        sM[tid] = s;
    }
    if (tid < 16) {
        float s = 0.0f;
#pragma unroll 8
        for (int i = 0; i < 128; i++) s += sWc[i * 32 + 16 + tid] * sB3[i];
        sV[tid] = s;
    }
    if (tid == 16) {
        float s = 0.0f;
#pragma unroll 8
        for (int i = 0; i < 128; i++) s += sB3[i] * sB3[i];
        sBB = s;
    }

    const int rowbase = blockIdx.x * NTHR;
    const int n  = rowbase + tid;
    const float valid = (n < NS) ? 1.0f : 0.0f;

    // ---- fused 128->32 matvec via staged, coalesced x tiles ----
    ull A[16];
#pragma unroll
    for (int q = 0; q < 16; q++) A[q] = 0ull;
    float n1sq = 0.0f, xb3 = 0.0f;

#pragma unroll 1
    for (int t = 0; t < 8; t++) {
        __syncthreads();   // protect sX reuse (also covers the const-computation above on t=0)
        // stage 256 rows x 16 cols, coalesced float4 LDG
#pragma unroll
        for (int j = 0; j < 4; j++) {
            int idx = tid + j * NTHR;           // 0..1023
            int row = idx >> 2, ch = idx & 3;
            int rg = rowbase + row; if (rg >= NS) rg = NS - 1;
            const float4 v4 = *(const float4*)(x1 + (size_t)rg * 128 + t * 16 + ch * 4);
            float* d = sX + row * 17 + ch * 4;
            d[0] = v4.x; d[1] = v4.y; d[2] = v4.z; d[3] = v4.w;
        }
        __syncthreads();
        const float* xr = sX + tid * 17;
#pragma unroll
        for (int c = 0; c < 16; c++) {
            const float xc = xr[c];
            const int gc = t * 16 + c;
            n1sq = fmaf(xc, xc, n1sq);
            xb3  = fmaf(xc, sB3[gc], xb3);
            const ull px = pk2(xc, xc);
            const ulonglong2* w = (const ulonglong2*)(sWc + gc * 32);
#pragma unroll
            for (int q = 0; q < 8; q++) {
                ulonglong2 tw = w[q];
                ffma2(A[2 * q],     px, tw.x);
                ffma2(A[2 * q + 1], px, tw.y);
            }
        }
    }

    // ---- per-sample tail ----
    float enc[16], t16[16];
#pragma unroll
    for (int q = 0; q < 8; q++) {
        float a, b;
        upk(A[q], a, b);     enc[2 * q] = a; enc[2 * q + 1] = b;
        upk(A[8 + q], a, b); t16[2 * q] = a; t16[2 * q + 1] = b;
    }
    float h1[16];
#pragma unroll
    for (int j = 0; j < 16; j++) h1[j] = tanh_fast(enc[j] + sEB1[j]);
    float h2[8];
#pragma unroll
    for (int o = 0; o < 8; o++) {
        float sm = sEB2[o];
#pragma unroll
        for (int i = 0; i < 16; i++) sm += h1[i] * sEW2[i * 8 + o];
        h2[o] = tanh_fast(sm);
    }
    float s3 = sEB3;
#pragma unroll
    for (int i = 0; i < 8; i++) s3 += h2[i] * sEW3[i];
    const float zc0 = tanh_fast(s3);

    float g1[8];
#pragma unroll
    for (int o = 0; o < 8; o++) g1[o] = tanh_fast(sDB1[o] + zc0 * sDW1[o]);
    float g2[16];
    ull gp[8];
#pragma unroll
    for (int o = 0; o < 16; o++) {
        float sm = sDB2[o];
#pragma unroll
        for (int i = 0; i < 8; i++) sm += g1[i] * sDW2[i * 16 + o];
        g2[o] = tanh_fast(sm);
    }
#pragma unroll
    for (int q = 0; q < 8; q++) gp[q] = pk2(g2[2 * q], g2[2 * q + 1]);

    float dotv = xb3;
#pragma unroll
    for (int j = 0; j < 16; j++) dotv += g2[j] * t16[j];
    float n2sq = sBB;
#pragma unroll
    for (int j = 0; j < 16; j++) {
        ull acc = pk2(2.0f * sV[j], 0.0f);
        const ulonglong2* Mr = (const ulonglong2*)(sM + j * 16);
#pragma unroll
        for (int q = 0; q < 4; q++) {
            ulonglong2 m = Mr[q];
            ffma2(acc, gp[2 * q],     m.x);
            ffma2(acc, gp[2 * q + 1], m.y);
        }
        float pa, pb; upk(acc, pa, pb);
        n2sq += g2[j] * (pa + pb);
    }
    const float dsq = fmaxf(n1sq - 2.0f * dotv + n2sq, 0.0f);
    const float zc1 = dotv * rsqrtf(n1sq * n2sq);
    const float zc2 = sqrtf(dsq);

    if (n < NS) {
        g_z[n]          = zc0;
        g_z[NS + n]     = zc1;
        g_z[2 * NS + n] = zc2;
    }

    // estimator + softmax
    float gm[4];
    {
        float tt[8];
#pragma unroll
        for (int o = 0; o < 8; o++)
            tt[o] = tanh_fast(sTB1[o] + zc0 * sTW1[o] + zc1 * sTW1[8 + o] + zc2 * sTW1[16 + o]);
        float lg[4];
#pragma unroll
        for (int k = 0; k < 4; k++) {
            float sm = sTB2[k];
#pragma unroll
            for (int o = 0; o < 8; o++) sm += tt[o] * sTW2[o * 4 + k];
            lg[k] = sm;
        }
        float m = fmaxf(fmaxf(lg[0], lg[1]), fmaxf(lg[2], lg[3]));
        float e0 = __expf(lg[0] - m), e1 = __expf(lg[1] - m);
        float e2 = __expf(lg[2] - m), e3 = __expf(lg[3] - m);
        float inv = __fdividef(1.0f, e0 + e1 + e2 + e3) * valid;
        gm[0] = e0 * inv; gm[1] = e1 * inv; gm[2] = e2 * inv; gm[3] = e3 * inv;
    }
    const float dsv = dsq * valid;
    const float f[3] = {zc0, zc1, zc2};

    // ---- deterministic block reduction of 41 statistics ----
    {
        float s = warp_sum(dsv);
        if (lane == 0) sWred[0][wid] = s;
    }
#pragma unroll
    for (int k = 0; k < 4; k++) {
        float vv[10];
        vv[0] = gm[k];
#pragma unroll
        for (int d = 0; d < 3; d++) vv[1 + d] = gm[k] * f[d];
        int c = 4;
#pragma unroll
        for (int d = 0; d < 3; d++)
#pragma unroll
            for (int e = d; e < 3; e++) vv[c++] = gm[k] * f[d] * f[e];
#pragma unroll
        for (int q = 0; q < 10; q++) {
            float s = warp_sum(vv[q]);
            if (lane == 0) sWred[1 + k * 10 + q][wid] = s;
        }
    }
    __syncthreads();
    if (tid < NQ) {
        float s = 0.0f;
#pragma unroll
        for (int w = 0; w < 8; w++) s += sWred[tid][w];
        g_scratch[blockIdx.x * 48 + tid] = s;
    }

    // ---- last-block global reduce + GMM parameters (deterministic fixed order) ----
    __threadfence();
    __syncthreads();
    if (tid == 0) sIsLast = (atomicAdd(&g_cnt1, 1) == NB1 - 1);
    __syncthreads();
    if (!sIsLast) return;
    __threadfence();

    for (int q = wid; q < NQ; q += 8) {
        double s = 0.0;
        for (int b = lane; b < NB1; b += 32) s += (double)g_scratch[b * 48 + q];
        s = warp_dsum(s);
        if (lane == 0) sTot[q] = s;
    }
    __syncthreads();
    if (tid < 4) {
        const int k = tid;
        const double* T = sTot + 1 + k * 10;
        double S0 = T[0];
        double m0 = T[1] / S0, m1 = T[2] / S0, m2 = T[3] / S0;
        double s00 = T[4] / S0 - m0 * m0, s01 = T[5] / S0 - m0 * m1, s02 = T[6] / S0 - m0 * m2;
        double s11 = T[7] / S0 - m1 * m1, s12 = T[8] / S0 - m1 * m2, s22 = T[9] / S0 - m2 * m2;
        double c00 = s11 * s22 - s12 * s12;
        double c01 = s02 * s12 - s01 * s22;
        double c02 = s01 * s12 - s02 * s11;
        double det = s00 * c00 + s01 * c01 + s02 * c02;
        double inv = 1.0 / det;
        double phi = S0 / (double)NS;
        double ck = log(phi) - 0.5 * (3.0 * log(2.0 * M_PI) + log(det));
        g_params[k * 10 + 0] = (float)m0;
        g_params[k * 10 + 1] = (float)m1;
        g_params[k * 10 + 2] = (float)m2;
        g_params[k * 10 + 3] = (float)(c00 * inv);
        g_params[k * 10 + 4] = (float)(c01 * inv);
        g_params[k * 10 + 5] = (float)(c02 * inv);
        g_params[k * 10 + 6] = (float)((s00 * s22 - s02 * s02) * inv);
        g_params[k * 10 + 7] = (float)((s02 * s01 - s00 * s12) * inv);
        g_params[k * 10 + 8] = (float)((s00 * s11 - s01 * s01) * inv);
        g_params[k * 10 + 9] = (float)ck;
        sL3[k] = 1.0 / s00 + 1.0 / s11 + 1.0 / s22;
    }
    __syncthreads();
    if (tid == 0) {
        double loss1 = sTot[0] / (double)NS;
        g_params[40] = (float)(loss1 + 1e-4 * (sL3[0] + sL3[1] + sL3[2] + sL3[3]));
        __threadfence();
        g_cnt1 = 0;                 // self-reset for next graph replay
    }
}

// ---------------- K3: per-sample energy + (last block) final loss ----------------
__global__ __launch_bounds__(NTHR) void k3(float* __restrict__ out, int out_size) {
    __shared__ float p[48];
    __shared__ float sw[8];
    __shared__ int sIsLast;
    const int tid = threadIdx.x;
    const int lane = tid & 31, wid = tid >> 5;
    if (tid < 41) p[tid] = g_params[tid];
    __syncthreads();
    const int n = blockIdx.x * NTHR + tid;
    const int ns = (n < NS) ? n : (NS - 1);
    const float zc0 = g_z[ns], zc1 = g_z[NS + ns], zc2 = g_z[2 * NS + ns];
    float e = 0.0f;
#pragma unroll
    for (int k = 0; k < 4; k++) {
        const float* P = p + k * 10;
        float v0 = zc0 - P[0], v1 = zc1 - P[1], v2 = zc2 - P[2];
        float q = v0 * v0 * P[3] + v1 * v1 * P[6] + v2 * v2 * P[8]
                + 2.0f * (v0 * v1 * P[4] + v0 * v2 * P[5] + v1 * v2 * P[7]);
        e += 0.5f * q - P[9];
    }
    if (n < NS) out[n] = e;
    float ev = (n < NS) ? e : 0.0f;
    float s = warp_sum(ev);
    if (lane == 0) sw[wid] = s;
    __syncthreads();
    if (tid == 0) {
        float t = 0.0f;
#pragma unroll
        for (int w = 0; w < 8; w++) t += sw[w];
        g_esum[blockIdx.x] = t;
    }
    __threadfence();
    __syncthreads();
    if (tid == 0) sIsLast = (atomicAdd(&g_cnt3, 1) == NB3 - 1);
    __syncthreads();
    if (!sIsLast) return;
    __threadfence();
    if (wid == 0) {
        double a = 0.0;
        for (int b = lane; b < NB3; b += 32) a += (double)g_esum[b];
        a = warp_dsum(a);
        if (lane == 0) {
            if (out_size > NS)
                out[NS] = p[40] + (float)(0.01 * (a / (double)NS));
            __threadfence();
            g_cnt3 = 0;             // self-reset for next graph replay
        }
    }
}

extern "C" void kernel_launch(void* const* d_in, const int* in_sizes, int n_in,
                              void* d_out, int out_size) {
    const float* x1  = (const float*)d_in[0];
    const float* ew1 = (const float*)d_in[1];
    const float* eb1 = (const float*)d_in[2];
    const float* ew2 = (const float*)d_in[3];
    const float* eb2 = (const float*)d_in[4];
    const float* ew3 = (const float*)d_in[5];
    const float* eb3 = (const float*)d_in[6];
    const float* dw1 = (const float*)d_in[7];
    const float* db1 = (const float*)d_in[8];
    const float* dw2 = (const float*)d_in[9];
    const float* db2 = (const float*)d_in[10];
    const float* dw3 = (const float*)d_in[11];
    const float* db3 = (const float*)d_in[12];
    const float* tw1 = (const float*)d_in[13];
    const float* tb1 = (const float*)d_in[14];
    const float* tw2 = (const float*)d_in[15];
    const float* tb2 = (const float*)d_in[16];
    float* out = (float*)d_out;

    k1<<<NB1, NTHR>>>(x1, ew1, eb1, ew2, eb2, ew3, eb3,
                      dw1, db1, dw2, db2, dw3, db3,
                      tw1, tb1, tw2, tb2);
    k3<<<NB3, NTHR>>>(out, out_size);
}

// round 6
// speedup vs baseline: 1.6802x; 1.6802x over previous
#include <cuda_runtime.h>
#include <cstdint>
#include <math.h>

#define NS   400000
#define NTHR 256
#define NBH  782                 // blocks per half kernel (782*256 = 200192)
#define NB1  (2*NBH)             // total stat blocks = 1564
#define NB3  1563                // energy blocks
#define NQ   41                  // 1 (loss1) + 4*10 GMM stats

// ---------------- device scratch (no allocations allowed) ----------------
__device__ float g_scratch[NB1 * 48];   // per-block stat partials
__device__ float g_z[3 * NS];           // z components, SoA
__device__ float g_params[48];          // per-k params + loss partial
__device__ float g_esum[NB3];           // per-block energy partials
__device__ int   g_cnt1 = 0;            // last-block ticket for k1b (self-resetting)
__device__ int   g_cnt3 = 0;            // last-block ticket for k3

typedef unsigned long long ull;

// ---------------- helpers ----------------
__device__ __forceinline__ ull pk2(float a, float b) {
    ull r; asm("mov.b64 %0, {%1, %2};" : "=l"(r) : "f"(a), "f"(b)); return r;
}
__device__ __forceinline__ void upk(ull v, float& a, float& b) {
    asm("mov.b64 {%0, %1}, %2;" : "=f"(a), "=f"(b) : "l"(v));
}
__device__ __forceinline__ void ffma2(ull& d, ull a, ull b) {
    asm("fma.rn.f32x2 %0, %1, %2, %0;" : "+l"(d) : "l"(a), "l"(b));
}
__device__ __forceinline__ float tanh_fast(float x) {
    float e = __expf(2.0f * x);
    return 1.0f - __fdividef(2.0f, e + 1.0f);
}
__device__ __forceinline__ float warp_sum(float v) {
#pragma unroll
    for (int o = 16; o > 0; o >>= 1) v += __shfl_down_sync(0xffffffffu, v, o);
    return v;
}
__device__ __forceinline__ double warp_dsum(double v) {
#pragma unroll
    for (int o = 16; o > 0; o >>= 1) v += __shfl_down_sync(0xffffffffu, v, o);
    return v;
}

// ---------------- K1: fused forward + stats (half grid; k1b finishes params) ----------------
__global__ __launch_bounds__(NTHR) void k1(
    const float* __restrict__ x1,
    const float* __restrict__ ew1, const float* __restrict__ eb1,
    const float* __restrict__ ew2, const float* __restrict__ eb2,
    const float* __restrict__ ew3, const float* __restrict__ eb3,
    const float* __restrict__ dw1, const float* __restrict__ db1,
    const float* __restrict__ dw2, const float* __restrict__ db2,
    const float* __restrict__ dw3, const float* __restrict__ db3,
    const float* __restrict__ tw1, const float* __restrict__ tb1,
    const float* __restrict__ tw2, const float* __restrict__ tb2,
    int blk_off, int do_final)
{
    __shared__ __align__(16) float sWc[4096];      // [128][32]: [enc_w1 | dec_w3^T]
    __shared__ float sX[8 * 544];                  // per-warp 32x17 staged x tile
    __shared__ __align__(16) float sM[256];        // dec_w3 @ dec_w3^T
    __shared__ __align__(16) float sB3[128];
    __shared__ float sV[16];
    __shared__ float sEB1[16], sEW2[128], sEB2[8], sEW3[8];
    __shared__ float sDW1[8], sDB1[8], sDW2[128], sDB2[16];
    __shared__ float sTW1[24], sTB1[8], sTW2[32], sTB2[4];
    __shared__ float sEB3, sBB;
    __shared__ float sWred[NQ][8];
    __shared__ double sTot[NQ];
    __shared__ double sL3[4];
    __shared__ int sIsLast;

    const int tid = threadIdx.x;
    const int lane = tid & 31, wid = tid >> 5;

    // ---- load weights (fused layout built on the fly) ----
    for (int idx = tid; idx < 4096; idx += NTHR) {
        int i = idx >> 5, c = idx & 31;
        sWc[idx] = (c < 16) ? ew1[i * 16 + c] : dw3[(c - 16) * 128 + i];
    }
    if (tid < 128) { sB3[tid] = db3[tid]; sEW2[tid] = ew2[tid]; sDW2[tid] = dw2[tid]; }
    if (tid < 16)  { sEB1[tid] = eb1[tid]; sDB2[tid] = db2[tid]; }
    if (tid < 8)   { sEB2[tid] = eb2[tid]; sEW3[tid] = ew3[tid];
                     sDW1[tid] = dw1[tid]; sDB1[tid] = db1[tid]; sTB1[tid] = tb1[tid]; }
    if (tid < 24)  sTW1[tid] = tw1[tid];
    if (tid < 32)  sTW2[tid] = tw2[tid];
    if (tid < 4)   sTB2[tid] = tb2[tid];
    if (tid == 0)  sEB3 = eb3[0];
    __syncthreads();

    // ---- per-block decoder-algebra constants (cheap, from smem) ----
    {
        int j = tid >> 4, l = tid & 15;
        float s = 0.0f;
#pragma unroll 8
        for (int i = 0; i < 128; i++)
            s += sWc[i * 32 + 16 + j] * sWc[i * 32 + 16 + l];
        sM[tid] = s;
    }
    if (tid < 16) {
        float s = 0.0f;
#pragma unroll 8
        for (int i = 0; i < 128; i++) s += sWc[i * 32 + 16 + tid] * sB3[i];
        sV[tid] = s;
    }
    if (tid == 16) {
        float s = 0.0f;
#pragma unroll 8
        for (int i = 0; i < 128; i++) s += sB3[i] * sB3[i];
        sBB = s;
    }
    __syncthreads();   // sM/sV/sBB visible for the tail; no more block barriers until stats

    const int gbid = blockIdx.x + blk_off;
    const int rowbase = gbid * NTHR;
    const int n = rowbase + tid;
    const float valid = (n < NS) ? 1.0f : 0.0f;

    float* const sXw = sX + wid * 544;
    const float* const xrow = sXw + lane * 17;
    const int r0 = lane >> 2, ch = lane & 3;

    // ---- fused 128->32 matvec: warp-private staged tiles, syncwarp only ----
    ull A[16];
#pragma unroll
    for (int q = 0; q < 16; q++) A[q] = 0ull;
    float n1sq = 0.0f, xb3 = 0.0f;

#pragma unroll 1
    for (int t = 0; t < 8; t++) {
        // stage this warp's 32 rows x 16 cols, coalesced float4 LDG (8 lines/wavefront)
#pragma unroll
        for (int j = 0; j < 4; j++) {
            int row = r0 + j * 8;
            int rg = rowbase + wid * 32 + row; if (rg >= NS) rg = NS - 1;
            const float4 v = *(const float4*)(x1 + (size_t)rg * 128 + t * 16 + ch * 4);
            float* d = sXw + row * 17 + ch * 4;
            d[0] = v.x; d[1] = v.y; d[2] = v.z; d[3] = v.w;
        }
        __syncwarp();
#pragma unroll
        for (int c = 0; c < 16; c++) {
            const float xc = xrow[c];
            const int gc = t * 16 + c;
            n1sq = fmaf(xc, xc, n1sq);
            xb3  = fmaf(xc, sB3[gc], xb3);
            const ull px = pk2(xc, xc);
            const ulonglong2* w = (const ulonglong2*)(sWc + gc * 32);
#pragma unroll
            for (int q = 0; q < 8; q++) {
                ulonglong2 tw = w[q];
                ffma2(A[2 * q],     px, tw.x);
                ffma2(A[2 * q + 1], px, tw.y);
            }
        }
        __syncwarp();   // protect sXw before next stage overwrites
    }

    // ---- per-sample tail ----
    float enc[16], t16[16];
#pragma unroll
    for (int q = 0; q < 8; q++) {
        float a, b;
        upk(A[q], a, b);     enc[2 * q] = a; enc[2 * q + 1] = b;
        upk(A[8 + q], a, b); t16[2 * q] = a; t16[2 * q + 1] = b;
    }
    float h1[16];
#pragma unroll
    for (int j = 0; j < 16; j++) h1[j] = tanh_fast(enc[j] + sEB1[j]);
    float h2[8];
#pragma unroll
    for (int o = 0; o < 8; o++) {
        float sm = sEB2[o];
#pragma unroll
        for (int i = 0; i < 16; i++) sm += h1[i] * sEW2[i * 8 + o];
        h2[o] = tanh_fast(sm);
    }
    float s3 = sEB3;
#pragma unroll
    for (int i = 0; i < 8; i++) s3 += h2[i] * sEW3[i];
    const float zc0 = tanh_fast(s3);

    float g1[8];
#pragma unroll
    for (int o = 0; o < 8; o++) g1[o] = tanh_fast(sDB1[o] + zc0 * sDW1[o]);
    float g2[16];
    ull gp[8];
#pragma unroll
    for (int o = 0; o < 16; o++) {
        float sm = sDB2[o];
#pragma unroll
        for (int i = 0; i < 8; i++) sm += g1[i] * sDW2[i * 16 + o];
        g2[o] = tanh_fast(sm);
    }
#pragma unroll
    for (int q = 0; q < 8; q++) gp[q] = pk2(g2[2 * q], g2[2 * q + 1]);

    float dotv = xb3;
#pragma unroll
    for (int j = 0; j < 16; j++) dotv += g2[j] * t16[j];
    float n2sq = sBB;
#pragma unroll
    for (int j = 0; j < 16; j++) {
        ull acc = pk2(2.0f * sV[j], 0.0f);
        const ulonglong2* Mr = (const ulonglong2*)(sM + j * 16);
#pragma unroll
        for (int q = 0; q < 4; q++) {
            ulonglong2 m = Mr[q];
            ffma2(acc, gp[2 * q],     m.x);
            ffma2(acc, gp[2 * q + 1], m.y);
        }
        float pa, pb; upk(acc, pa, pb);
        n2sq += g2[j] * (pa + pb);
    }
    const float dsq = fmaxf(n1sq - 2.0f * dotv + n2sq, 0.0f);
    const float zc1 = dotv * rsqrtf(n1sq * n2sq);
    const float zc2 = sqrtf(dsq);

    if (n < NS) {
        g_z[n]          = zc0;
        g_z[NS + n]     = zc1;
        g_z[2 * NS + n] = zc2;
    }

    // estimator + softmax
    float gm[4];
    {
        float tt[8];
#pragma unroll
        for (int o = 0; o < 8; o++)
            tt[o] = tanh_fast(sTB1[o] + zc0 * sTW1[o] + zc1 * sTW1[8 + o] + zc2 * sTW1[16 + o]);
        float lg[4];
#pragma unroll
        for (int k = 0; k < 4; k++) {
            float sm = sTB2[k];
#pragma unroll
            for (int o = 0; o < 8; o++) sm += tt[o] * sTW2[o * 4 + k];
            lg[k] = sm;
        }
        float m = fmaxf(fmaxf(lg[0], lg[1]), fmaxf(lg[2], lg[3]));
        float e0 = __expf(lg[0] - m), e1 = __expf(lg[1] - m);
        float e2 = __expf(lg[2] - m), e3 = __expf(lg[3] - m);
        float inv = __fdividef(1.0f, e0 + e1 + e2 + e3) * valid;
        gm[0] = e0 * inv; gm[1] = e1 * inv; gm[2] = e2 * inv; gm[3] = e3 * inv;
    }
    const float dsv = dsq * valid;
    const float f[3] = {zc0, zc1, zc2};

    // ---- deterministic block reduction of 41 statistics ----
    {
        float s = warp_sum(dsv);
        if (lane == 0) sWred[0][wid] = s;
    }
#pragma unroll
    for (int k = 0; k < 4; k++) {
        float vv[10];
        vv[0] = gm[k];
#pragma unroll
        for (int d = 0; d < 3; d++) vv[1 + d] = gm[k] * f[d];
        int c = 4;
#pragma unroll
        for (int d = 0; d < 3; d++)
#pragma unroll
            for (int e = d; e < 3; e++) vv[c++] = gm[k] * f[d] * f[e];
#pragma unroll
        for (int q = 0; q < 10; q++) {
            float s = warp_sum(vv[q]);
            if (lane == 0) sWred[1 + k * 10 + q][wid] = s;
        }
    }
    __syncthreads();
    if (tid < NQ) {
        float s = 0.0f;
#pragma unroll
        for (int w = 0; w < 8; w++) s += sWred[tid][w];
        g_scratch[gbid * 48 + tid] = s;
    }

    if (!do_final) return;

    // ---- last block of k1b: global stat reduce + GMM params (deterministic order) ----
    __threadfence();
    __syncthreads();
    if (tid == 0) sIsLast = (atomicAdd(&g_cnt1, 1) == NBH - 1);
    __syncthreads();
    if (!sIsLast) return;
    __threadfence();

    for (int q = wid; q < NQ; q += 8) {
        double s = 0.0;
        for (int b = lane; b < NB1; b += 32) s += (double)g_scratch[b * 48 + q];
        s = warp_dsum(s);
        if (lane == 0) sTot[q] = s;
    }
    __syncthreads();
    if (tid < 4) {
        const int k = tid;
        const double* T = sTot + 1 + k * 10;
        double S0 = T[0];
        double m0 = T[1] / S0, m1 = T[2] / S0, m2 = T[3] / S0;
        double s00 = T[4] / S0 - m0 * m0, s01 = T[5] / S0 - m0 * m1, s02 = T[6] / S0 - m0 * m2;
        double s11 = T[7] / S0 - m1 * m1, s12 = T[8] / S0 - m1 * m2, s22 = T[9] / S0 - m2 * m2;
        double c00 = s11 * s22 - s12 * s12;
        double c01 = s02 * s12 - s01 * s22;
        double c02 = s01 * s12 - s02 * s11;
        double det = s00 * c00 + s01 * c01 + s02 * c02;
        double inv = 1.0 / det;
        double phi = S0 / (double)NS;
        double ck = log(phi) - 0.5 * (3.0 * log(2.0 * M_PI) + log(det));
        g_params[k * 10 + 0] = (float)m0;
        g_params[k * 10 + 1] = (float)m1;
        g_params[k * 10 + 2] = (float)m2;
        g_params[k * 10 + 3] = (float)(c00 * inv);
        g_params[k * 10 + 4] = (float)(c01 * inv);
        g_params[k * 10 + 5] = (float)(c02 * inv);
        g_params[k * 10 + 6] = (float)((s00 * s22 - s02 * s02) * inv);
        g_params[k * 10 + 7] = (float)((s02 * s01 - s00 * s12) * inv);
        g_params[k * 10 + 8] = (float)((s00 * s11 - s01 * s01) * inv);
        g_params[k * 10 + 9] = (float)ck;
        sL3[k] = 1.0 / s00 + 1.0 / s11 + 1.0 / s22;
    }
    __syncthreads();
    if (tid == 0) {
        double loss1 = sTot[0] / (double)NS;
        g_params[40] = (float)(loss1 + 1e-4 * (sL3[0] + sL3[1] + sL3[2] + sL3[3]));
        __threadfence();
        g_cnt1 = 0;                 // self-reset for next graph replay
    }
}

// ---------------- K3: per-sample energy + (last block) final loss ----------------
__global__ __launch_bounds__(NTHR) void k3(float* __restrict__ out, int out_size) {
    __shared__ float p[48];
    __shared__ float sw[8];
    __shared__ int sIsLast;
    const int tid = threadIdx.x;
    const int lane = tid & 31, wid = tid >> 5;
    if (tid < 41) p[tid] = g_params[tid];
    __syncthreads();
    const int n = blockIdx.x * NTHR + tid;
    const int ns = (n < NS) ? n : (NS - 1);
    const float zc0 = g_z[ns], zc1 = g_z[NS + ns], zc2 = g_z[2 * NS + ns];
    float e = 0.0f;
#pragma unroll
    for (int k = 0; k < 4; k++) {
        const float* P = p + k * 10;
        float v0 = zc0 - P[0], v1 = zc1 - P[1], v2 = zc2 - P[2];
        float q = v0 * v0 * P[3] + v1 * v1 * P[6] + v2 * v2 * P[8]
                + 2.0f * (v0 * v1 * P[4] + v0 * v2 * P[5] + v1 * v2 * P[7]);
        e += 0.5f * q - P[9];
    }
    if (n < NS) out[n] = e;
    float ev = (n < NS) ? e : 0.0f;
    float s = warp_sum(ev);
    if (lane == 0) sw[wid] = s;
    __syncthreads();
    if (tid == 0) {
        float t = 0.0f;
#pragma unroll
        for (int w = 0; w < 8; w++) t += sw[w];
        g_esum[blockIdx.x] = t;
    }
    __threadfence();
    __syncthreads();
    if (tid == 0) sIsLast = (atomicAdd(&g_cnt3, 1) == NB3 - 1);
    __syncthreads();
    if (!sIsLast) return;
    __threadfence();
    if (wid == 0) {
        double a = 0.0;
        for (int b = lane; b < NB3; b += 32) a += (double)g_esum[b];
        a = warp_dsum(a);
        if (lane == 0) {
            if (out_size > NS)
                out[NS] = p[40] + (float)(0.01 * (a / (double)NS));
            __threadfence();
            g_cnt3 = 0;             // self-reset for next graph replay
        }
    }
}

extern "C" void kernel_launch(void* const* d_in, const int* in_sizes, int n_in,
                              void* d_out, int out_size) {
    const float* x1  = (const float*)d_in[0];
    const float* ew1 = (const float*)d_in[1];
    const float* eb1 = (const float*)d_in[2];
    const float* ew2 = (const float*)d_in[3];
    const float* eb2 = (const float*)d_in[4];
    const float* ew3 = (const float*)d_in[5];
    const float* eb3 = (const float*)d_in[6];
    const float* dw1 = (const float*)d_in[7];
    const float* db1 = (const float*)d_in[8];
    const float* dw2 = (const float*)d_in[9];
    const float* db2 = (const float*)d_in[10];
    const float* dw3 = (const float*)d_in[11];
    const float* db3 = (const float*)d_in[12];
    const float* tw1 = (const float*)d_in[13];
    const float* tb1 = (const float*)d_in[14];
    const float* tw2 = (const float*)d_in[15];
    const float* tb2 = (const float*)d_in[16];
    float* out = (float*)d_out;

    k1<<<NBH, NTHR>>>(x1, ew1, eb1, ew2, eb2, ew3, eb3,
                      dw1, db1, dw2, db2, dw3, db3,
                      tw1, tb1, tw2, tb2, 0, 0);
    k1<<<NBH, NTHR>>>(x1, ew1, eb1, ew2, eb2, ew3, eb3,
                      dw1, db1, dw2, db2, dw3, db3,
                      tw1, tb1, tw2, tb2, NBH, 1);
    k3<<<NB3, NTHR>>>(out, out_size);
}